// round 3
// baseline (speedup 1.0000x reference)
#include <cuda_runtime.h>
#include <cstdint>

// probs: float32 [50,50,50,50] -> 6,250,000 floats (row-major)
// X:     int32   [8,000,000, 4]
// out:   float32 [8,000,000]
//
// out[i] = probs[ ((X0*50 + X1)*50 + X2)*50 + X3 ]
//
// Block-cyclic 4x unroll: each thread handles 4 samples spaced 256 apart,
// so every LDG.128 (X) and STG.32 (out) stays perfectly coalesced while the
// thread carries 4 independent X-loads + 4 independent gathers in flight.

constexpr int THREADS = 256;
constexpr int UNROLL  = 4;
constexpr int TILE    = THREADS * UNROLL;  // 1024 samples per block

__global__ __launch_bounds__(THREADS) void joint_cat_gather4(
    const float* __restrict__ probs,
    const int4* __restrict__ X,
    float* __restrict__ out,
    int n)
{
    int base = blockIdx.x * TILE + threadIdx.x;

    // Fast path: full tile (no bounds checks)
    if (base + (UNROLL - 1) * THREADS < n) {
        int4 x[UNROLL];
#pragma unroll
        for (int k = 0; k < UNROLL; k++)
            x[k] = X[base + k * THREADS];          // 4 independent coalesced 16B loads

        int idx[UNROLL];
#pragma unroll
        for (int k = 0; k < UNROLL; k++)
            idx[k] = ((x[k].x * 50 + x[k].y) * 50 + x[k].z) * 50 + x[k].w;

        float r[UNROLL];
#pragma unroll
        for (int k = 0; k < UNROLL; k++)
            r[k] = __ldg(probs + idx[k]);          // 4 independent gathers in flight

#pragma unroll
        for (int k = 0; k < UNROLL; k++)
            out[base + k * THREADS] = r[k];        // coalesced stores
    } else {
        // Tail: per-element guard
#pragma unroll
        for (int k = 0; k < UNROLL; k++) {
            int i = base + k * THREADS;
            if (i < n) {
                int4 x = X[i];
                int idx = ((x.x * 50 + x.y) * 50 + x.z) * 50 + x.w;
                out[i] = __ldg(probs + idx);
            }
        }
    }
}

extern "C" void kernel_launch(void* const* d_in, const int* in_sizes, int n_in,
                              void* d_out, int out_size)
{
    const float* probs = (const float*)d_in[0];
    const int4* X = (const int4*)d_in[1];
    float* out = (float*)d_out;

    int n = out_size;  // 8,000,000 samples
    int blocks = (n + TILE - 1) / TILE;
    joint_cat_gather4<<<blocks, THREADS>>>(probs, X, out, n);
}

// round 4
// speedup vs baseline: 1.0067x; 1.0067x over previous
#include <cuda_runtime.h>
#include <cstdint>

// probs: float32 [50,50,50,50] -> 6,250,000 floats (row-major)
// X:     int32   [8,000,000, 4]
// out:   float32 [8,000,000]
//
// out[i] = probs[ ((X0*50 + X1)*50 + X2)*50 + X3 ]
//
// Key trick: the random gather is issued as QUARTER-WARP predicated LDGs
// (8 active lanes per instruction) instead of full-warp LDGs. Total L1
// wavefronts are identical, but each instruction's divergent-address replay
// chain is 4x shorter, so the L1tex coalescer pipelines across instructions
// at ~1 cyc/wavefront instead of serializing ~2 cyc/replay within one LDG.

constexpr int THREADS = 256;
constexpr int UNROLL  = 4;
constexpr int TILE    = THREADS * UNROLL;  // 1024 samples per block

__global__ __launch_bounds__(THREADS) void joint_cat_gather_q(
    const float* __restrict__ probs,
    const int4* __restrict__ X,
    float* __restrict__ out,
    int n)
{
    int base = blockIdx.x * TILE + threadIdx.x;
    int lane_group = (threadIdx.x & 31) >> 3;   // 0..3: lanes 0-7, 8-15, 16-23, 24-31

    if (base + (UNROLL - 1) * THREADS < n) {
        // ---- fast path: full tile ----
        int4 x[UNROLL];
#pragma unroll
        for (int k = 0; k < UNROLL; k++)
            x[k] = X[base + k * THREADS];              // coalesced 16B loads

        int idx[UNROLL];
#pragma unroll
        for (int k = 0; k < UNROLL; k++)
            idx[k] = ((x[k].x * 50 + x[k].y) * 50 + x[k].z) * 50 + x[k].w;

        float r[UNROLL];
        // 16 predicated LDGs, each with 8 active lanes -> 8 wavefronts apiece.
#pragma unroll
        for (int j = 0; j < 4; j++) {
#pragma unroll
            for (int k = 0; k < UNROLL; k++) {
                if (lane_group == j)
                    r[k] = __ldg(probs + idx[k]);
            }
        }

#pragma unroll
        for (int k = 0; k < UNROLL; k++)
            out[base + k * THREADS] = r[k];            // coalesced stores
    } else {
        // ---- tail: per-element guard ----
#pragma unroll
        for (int k = 0; k < UNROLL; k++) {
            int i = base + k * THREADS;
            if (i < n) {
                int4 x = X[i];
                int idx = ((x.x * 50 + x.y) * 50 + x.z) * 50 + x.w;
                out[i] = __ldg(probs + idx);
            }
        }
    }
}

extern "C" void kernel_launch(void* const* d_in, const int* in_sizes, int n_in,
                              void* d_out, int out_size)
{
    const float* probs = (const float*)d_in[0];
    const int4* X = (const int4*)d_in[1];
    float* out = (float*)d_out;

    int n = out_size;  // 8,000,000 samples
    int blocks = (n + TILE - 1) / TILE;
    joint_cat_gather_q<<<blocks, THREADS>>>(probs, X, out, n);
}

// round 5
// speedup vs baseline: 1.0447x; 1.0377x over previous
#include <cuda_runtime.h>
#include <cstdint>

// probs: float32 [50,50,50,50] -> 6,250,000 floats (row-major)
// X:     int32   [8,000,000, 4]
// out:   float32 [8,000,000]
//
// out[i] = probs[ ((X0*50 + X1)*50 + X2)*50 + X3 ]
//
// Cache-op tuned:
//  - gathers use __ldcg (L2-only): ~0% L1 hit rate on a 25MB table means L1
//    fills are pure waste of L1 bandwidth + pollution. Keep the table in L2.
//  - X reads use __ldcs (streaming, evict-first): zero reuse.
//  - out stores use __stcs (streaming): no write-allocate pollution.
// Quarter-warp predicated gathers retained (shorter replay chains per LDG).

constexpr int THREADS = 256;
constexpr int UNROLL  = 4;
constexpr int TILE    = THREADS * UNROLL;  // 1024 samples per block

__global__ __launch_bounds__(THREADS) void joint_cat_gather_cg(
    const float* __restrict__ probs,
    const int4* __restrict__ X,
    float* __restrict__ out,
    int n)
{
    int base = blockIdx.x * TILE + threadIdx.x;
    int lane_group = (threadIdx.x & 31) >> 3;   // 0..3

    if (base + (UNROLL - 1) * THREADS < n) {
        // ---- fast path: full tile ----
        int4 x[UNROLL];
#pragma unroll
        for (int k = 0; k < UNROLL; k++)
            x[k] = __ldcs(&X[base + k * THREADS]);     // streaming coalesced 16B loads

        int idx[UNROLL];
#pragma unroll
        for (int k = 0; k < UNROLL; k++)
            idx[k] = ((x[k].x * 50 + x[k].y) * 50 + x[k].z) * 50 + x[k].w;

        float r[UNROLL];
        // 16 predicated LDG.cg, each with 8 active lanes.
#pragma unroll
        for (int j = 0; j < 4; j++) {
#pragma unroll
            for (int k = 0; k < UNROLL; k++) {
                if (lane_group == j)
                    r[k] = __ldcg(probs + idx[k]);     // L2-only gather, no L1 fill
            }
        }

#pragma unroll
        for (int k = 0; k < UNROLL; k++)
            __stcs(&out[base + k * THREADS], r[k]);    // streaming coalesced stores
    } else {
        // ---- tail: per-element guard ----
#pragma unroll
        for (int k = 0; k < UNROLL; k++) {
            int i = base + k * THREADS;
            if (i < n) {
                int4 x = __ldcs(&X[i]);
                int idx = ((x.x * 50 + x.y) * 50 + x.z) * 50 + x.w;
                __stcs(&out[i], __ldcg(probs + idx));
            }
        }
    }
}

extern "C" void kernel_launch(void* const* d_in, const int* in_sizes, int n_in,
                              void* d_out, int out_size)
{
    const float* probs = (const float*)d_in[0];
    const int4* X = (const int4*)d_in[1];
    float* out = (float*)d_out;

    int n = out_size;  // 8,000,000 samples
    int blocks = (n + TILE - 1) / TILE;
    joint_cat_gather_cg<<<blocks, THREADS>>>(probs, X, out, n);
}

// round 6
// speedup vs baseline: 1.0610x; 1.0156x over previous
#include <cuda_runtime.h>
#include <cstdint>

// probs: float32 [50,50,50,50] -> 6,250,000 floats (row-major)
// X:     int32   [8,000,000, 4]
// out:   float32 [8,000,000]
//
// out[i] = probs[ ((X0*50 + X1)*50 + X2)*50 + X3 ]
//
// The X stream is loaded per-block via 1D bulk TMA (cp.async.bulk) into SMEM,
// freeing the LSU's outstanding-miss slots and L1 wavefront slots so they are
// spent (almost) exclusively on the 8M random gathers. Gathers stay L2-only
// (__ldcg); outputs are streaming stores.

constexpr int THREADS = 256;
constexpr int UNROLL  = 4;
constexpr int TILE    = THREADS * UNROLL;  // 1024 samples per block (16 KB of X)

__global__ __launch_bounds__(THREADS) void joint_cat_tma(
    const float* __restrict__ probs,
    const int4* __restrict__ X,
    float* __restrict__ out,
    int n)
{
    __shared__ alignas(128) int4 xs[TILE];
    __shared__ alignas(8) unsigned long long mbar;

    int tid = threadIdx.x;
    long long base = (long long)blockIdx.x * TILE;
    int count = n - (int)base;                 // samples this block owns
    if (count > TILE) count = TILE;
    unsigned bytes = (unsigned)count * 16u;    // always a multiple of 16

    unsigned mbar_addr = (unsigned)__cvta_generic_to_shared(&mbar);
    unsigned xs_addr   = (unsigned)__cvta_generic_to_shared(xs);

    if (tid == 0) {
        asm volatile("mbarrier.init.shared.b64 [%0], 1;"
                     :: "r"(mbar_addr) : "memory");
    }
    __syncthreads();

    if (tid == 0) {
        asm volatile("mbarrier.arrive.expect_tx.shared.b64 _, [%0], %1;"
                     :: "r"(mbar_addr), "r"(bytes) : "memory");
        asm volatile(
            "cp.async.bulk.shared::cta.global.mbarrier::complete_tx::bytes "
            "[%0], [%1], %2, [%3];"
            :: "r"(xs_addr), "l"(X + base), "r"(bytes), "r"(mbar_addr)
            : "memory");
    }

    // Wait for the TMA transaction (phase 0).
    {
        unsigned done;
        do {
            asm volatile(
                "{\n\t.reg .pred p;\n\t"
                "mbarrier.try_wait.parity.acquire.cta.shared::cta.b64 p, [%1], 0;\n\t"
                "selp.b32 %0, 1, 0, p;\n\t}"
                : "=r"(done) : "r"(mbar_addr) : "memory");
        } while (!done);
    }

    int lane_group = (tid & 31) >> 3;  // 0..3 (quarter-warp gather issue)

    if (count == TILE) {
        // ---- fast path: full tile ----
        int4 x[UNROLL];
#pragma unroll
        for (int k = 0; k < UNROLL; k++)
            x[k] = xs[k * THREADS + tid];                 // LDS, no miss slots

        int idx[UNROLL];
#pragma unroll
        for (int k = 0; k < UNROLL; k++)
            idx[k] = ((x[k].x * 50 + x[k].y) * 50 + x[k].z) * 50 + x[k].w;

        float r[UNROLL];
#pragma unroll
        for (int j = 0; j < 4; j++) {
#pragma unroll
            for (int k = 0; k < UNROLL; k++) {
                if (lane_group == j)
                    r[k] = __ldcg(probs + idx[k]);        // L2-only gather
            }
        }

#pragma unroll
        for (int k = 0; k < UNROLL; k++)
            __stcs(&out[base + k * THREADS + tid], r[k]); // streaming stores
    } else {
        // ---- tail tile ----
#pragma unroll
        for (int k = 0; k < UNROLL; k++) {
            int j = k * THREADS + tid;
            if (j < count) {
                int4 x = xs[j];
                int idx = ((x.x * 50 + x.y) * 50 + x.z) * 50 + x.w;
                __stcs(&out[base + j], __ldcg(probs + idx));
            }
        }
    }
}

extern "C" void kernel_launch(void* const* d_in, const int* in_sizes, int n_in,
                              void* d_out, int out_size)
{
    const float* probs = (const float*)d_in[0];
    const int4* X = (const int4*)d_in[1];
    float* out = (float*)d_out;

    int n = out_size;  // 8,000,000 samples
    int blocks = (n + TILE - 1) / TILE;
    joint_cat_tma<<<blocks, THREADS>>>(probs, X, out, n);
}